// round 16
// baseline (speedup 1.0000x reference)
#include <cuda_runtime.h>
#include <cuda_fp16.h>
#include <cstdint>

// Problem constants
#define NROWS 10000
#define KDIM  10000
#define KH    10240     // fp16 adj padded cols (zeros beyond 10000)
#define F     20        // hidden width
#define D     128       // in/out width
#define NSTRIPS ((NROWS + 15) / 16)   // 625 (exact)

// K-split over the padded fp16 matrix: 20 slabs of 512 cols (32 | 512)
#define SPLIT  20
#define SLAB   512
#define SSTEPS (SLAB / 32)      // 16 supersteps (2 fp16 MMAs x 3 n-tiles each)
#define TILE_HALVES (16 * SLAB) // 8192 halves = 16 KB per (strip,slab) tile
#define STRIPS_PER_BLK 8
#define NSTRIP_GROUPS ((NSTRIPS + STRIPS_PER_BLK - 1) / STRIPS_PER_BLK)  // 79
#define ASTAGES 3               // cp.async A pipeline depth (fp16 pass)

// fuse0 geometry: 6 warps/block so fp32 cp.async stages + B fit in 48 KB
#define F0_WARPS  6
#define F0_THREADS (F0_WARPS * 32)
#define F0_GROUPS ((NSTRIPS + F0_WARPS - 1) / F0_WARPS)   // 105
#define F0_STAGES 2

// Intra-tile offsets IN HALVES:
#define OFF_TIG   8
#define OFF_GID   32
#define OFF_HALF  256
#define OFF_SS    512

// B smem: half2 words, [kpair 256][col stride 22] -> conflict-free LDS
#define NSTRIDE 22
#define TS_WORDS (256 * NSTRIDE + 32)

// Scratch (no allocations allowed)
__device__ float  g_bufT[NROWS * F];
__device__ float  g_bufH[NROWS * F];
__device__ float  g_part[SPLIT * NROWS * F];        // 16 MB partials
// Tiled fp16 adj: [strip 625][slab 20][ss 16][half 2][gid 8][tig 4][8 halves]
__device__ __half g_adjh[(size_t)NROWS * KH];       // 204.8 MB

__device__ __forceinline__ uint32_t pack_h2(float a, float b) {
    __half2 h = __floats2half2_rn(a, b);
    return *(uint32_t*)&h;
}
__device__ __forceinline__ uint32_t smem_u32(const void* p) {
    return (uint32_t)__cvta_generic_to_shared(p);
}
__device__ __forceinline__ void cpa16(uint32_t saddr, const void* gptr) {
    asm volatile("cp.async.cg.shared.global [%0], [%1], 16;"
                 :: "r"(saddr), "l"(gptr));
}

// Vectorized B staging: Ts[kp*22 + c] = half2(T[2kp][c], T[2kp+1][c]).
// Item (kp, c4): 2 coalesced float4 loads, pack 4 half2, 2x uint2 STS.
template <int NT>
__device__ __forceinline__ void stage_B(const float* __restrict__ src,
                                        uint32_t* __restrict__ Ts, int tid)
{
#pragma unroll
    for (int it = 0; it < (1280 + NT - 1) / NT; ++it) {
        const int i = it * NT + tid;      // 0..1279
        if (i < 1280) {
            const int kp = i / 5;
            const int c4 = i % 5;
            const float4 f0 = *(const float4*)(src + kp * 40 + 4 * c4);
            const float4 f1 = *(const float4*)(src + kp * 40 + 20 + 4 * c4);
            uint2 lo, hi;
            lo.x = pack_h2(f0.x, f1.x); lo.y = pack_h2(f0.y, f1.y);
            hi.x = pack_h2(f0.z, f1.z); hi.y = pack_h2(f0.w, f1.w);
            uint32_t* dst = &Ts[kp * NSTRIDE + 4 * c4];
            *(uint2*)(dst)     = lo;
            *(uint2*)(dst + 2) = hi;
        }
    }
}

// ---------------------------------------------------------------------------
// PASS 0 (fused convert + GEMM): reads fp32 adj via a 2-stage cp.async
// pipeline, writes tiled fp16 copy, computes part[slab] = adj[:,slab]@T with
// fp16 m16n8k16. 6 warps/block; A stage = 4 conflict-free 512-B lane-linear
// regions (c0=row gid lo, c1=row gid hi, c2=row gid+8 lo, c3=row gid+8 hi).
// Pad cols >= KDIM: slot zeroed by STS instead of cp.async (prologue stages
// are always in-bounds: max prologue gc = 9728+32+24 = 9784 < 10000).
// ---------------------------------------------------------------------------
__global__ void __launch_bounds__(F0_THREADS, 4)
spmm_fuse0_kernel(const float* __restrict__ adj,
                  const float* __restrict__ T,
                  float* __restrict__ part)
{
    __shared__ uint32_t Ts[TS_WORDS];                        // 22.65 KB
    __shared__ __align__(16) float As[F0_WARPS][F0_STAGES][4][128];  // 24 KB

    const int tid  = threadIdx.x;
    const int warp = tid >> 5;
    const int lane = tid & 31;
    const int gid  = lane >> 2;
    const int tig  = lane & 3;
    const int tig2 = 2 * tig;

    if (tid < 32) Ts[256 * NSTRIDE + tid] = 0;

    const int strip  = blockIdx.x * F0_WARPS + warp;
    const bool active = (strip < NSTRIPS);
    const int m0   = strip * 16;
    const int slab = blockIdx.y;
    const int cbase = slab * SLAB;       // fp32 col base of this slab

    const float* a_row0 = adj + (size_t)(active ? (m0 + gid) : 0) * KDIM;
    const float* a_row1 = a_row0 + (size_t)8 * KDIM;
    __half* tile_w = g_adjh
        + ((size_t)(active ? strip : 0) * SPLIT + slab) * TILE_HALVES
        + lane * OFF_TIG;               // lane-linear write base

    const uint32_t asw = smem_u32(&As[warp][0][0][0]);  // stage stride 2048 B

    // prologue: fill both stages (always in-bounds, see header comment)
#pragma unroll
    for (int p = 0; p < F0_STAGES; p++) {
        if (active) {
            const int gc = cbase + 32 * p + 8 * tig;
            const uint32_t base = asw + p * 2048 + lane * 16;
            cpa16(base,        a_row0 + gc);
            cpa16(base + 512,  a_row0 + gc + 4);
            cpa16(base + 1024, a_row1 + gc);
            cpa16(base + 1536, a_row1 + gc + 4);
        }
        asm volatile("cp.async.commit_group;");
    }

    // stage B slab (vectorized) while A stream is in flight
    stage_B<F0_THREADS>(T + (size_t)slab * SLAB * F, Ts, tid);

    float acc[3][4];
#pragma unroll
    for (int t = 0; t < 3; t++)
#pragma unroll
        for (int j = 0; j < 4; j++) acc[t][j] = 0.0f;

    __syncthreads();   // B staging visible to all warps

    if (active) {
#pragma unroll
        for (int ss = 0; ss < SSTEPS; ++ss) {
            const int buf = ss & 1;

            // stage ss complete once <= F0_STAGES-1 groups remain pending
            asm volatile("cp.async.wait_group %0;" :: "n"(F0_STAGES - 1));

            const float4 f0a = *(const float4*)&As[warp][buf][0][lane * 4];
            const float4 f0b = *(const float4*)&As[warp][buf][1][lane * 4];
            const float4 f1a = *(const float4*)&As[warp][buf][2][lane * 4];
            const float4 f1b = *(const float4*)&As[warp][buf][3][lane * 4];

            // refill this buffer with stage ss+2 (LDS above already sampled;
            // same-thread program order makes the overwrite safe)
            {
                const int nss = ss + F0_STAGES;
                if (nss < SSTEPS) {
                    const int gc = cbase + 32 * nss + 8 * tig;
                    const uint32_t base = asw + buf * 2048 + lane * 16;
                    if (gc < KDIM) {   // 8-col group wholly valid or not
                        cpa16(base,        a_row0 + gc);
                        cpa16(base + 512,  a_row0 + gc + 4);
                        cpa16(base + 1024, a_row1 + gc);
                        cpa16(base + 1536, a_row1 + gc + 4);
                    } else {
                        const float4 z = make_float4(0.f, 0.f, 0.f, 0.f);
                        *(float4*)&As[warp][buf][0][lane * 4] = z;
                        *(float4*)&As[warp][buf][1][lane * 4] = z;
                        *(float4*)&As[warp][buf][2][lane * 4] = z;
                        *(float4*)&As[warp][buf][3][lane * 4] = z;
                    }
                }
            }
            asm volatile("cp.async.commit_group;");

            // convert: va/vb match the tiled layout's register image exactly
            uint4 va, vb;
            va.x = pack_h2(f0a.x, f0a.y); va.y = pack_h2(f0a.z, f0a.w);
            va.z = pack_h2(f0b.x, f0b.y); va.w = pack_h2(f0b.z, f0b.w);
            vb.x = pack_h2(f1a.x, f1a.y); vb.y = pack_h2(f1a.z, f1a.w);
            vb.z = pack_h2(f1b.x, f1b.y); vb.w = pack_h2(f1b.z, f1b.w);

            // tiled fp16 write (warp: 2 x 512 B contiguous, lane-linear)
            *(uint4*)(tile_w + ss * OFF_SS)            = va;
            *(uint4*)(tile_w + ss * OFF_SS + OFF_HALF) = vb;

            const int kpbase = (16 * ss + 4 * tig) * NSTRIDE;
#pragma unroll
            for (int m = 0; m < 2; m++) {
                const uint32_t a0 = (m == 0) ? va.x : va.z;
                const uint32_t a1 = (m == 0) ? vb.x : vb.z;
                const uint32_t a2 = (m == 0) ? va.y : va.w;
                const uint32_t a3 = (m == 0) ? vb.y : vb.w;
                const int r0 = kpbase + 2 * m * NSTRIDE;
#pragma unroll
                for (int t = 0; t < 3; t++) {
                    const int cn = 8 * t + gid;
                    const uint32_t b0 = Ts[r0 + cn];
                    const uint32_t b1 = Ts[r0 + NSTRIDE + cn];
                    asm volatile(
                        "mma.sync.aligned.m16n8k16.row.col.f32.f16.f16.f32 "
                        "{%0,%1,%2,%3},{%4,%5,%6,%7},{%8,%9},{%0,%1,%2,%3};"
                        : "+f"(acc[t][0]), "+f"(acc[t][1]),
                          "+f"(acc[t][2]), "+f"(acc[t][3])
                        : "r"(a0), "r"(a1), "r"(a2), "r"(a3),
                          "r"(b0), "r"(b1));
                }
            }
        }

        float* po = part + (size_t)slab * NROWS * F;
#pragma unroll
        for (int t = 0; t < 3; t++) {
            const int c = 8 * t + tig2;
            if (c < F) {
                const int r0 = m0 + gid;
                const int r1 = r0 + 8;
                *(float2*)(po + (size_t)r0 * F + c) =
                    make_float2(acc[t][0], acc[t][1]);
                *(float2*)(po + (size_t)r1 * F + c) =
                    make_float2(acc[t][2], acc[t][3]);
            }
        }
    }
}

// ---------------------------------------------------------------------------
// Big GEMM partial (fp16 m16n8k16, tiled adj): passes 2 and 3.
// A path: per-warp 3-stage cp.async pipeline into smem; sync is
// cp.async.wait_group only (each lane copies exactly the 16 B it consumes).
// ---------------------------------------------------------------------------
__global__ void __launch_bounds__(256, 4)
spmm_part_kernel(const float* __restrict__ T,
                 float* __restrict__ part)
{
    __shared__ uint32_t Ts[TS_WORDS];
    __shared__ __align__(16) __half As[STRIPS_PER_BLK][ASTAGES][512]; // 24 KB

    const int tid  = threadIdx.x;
    const int warp = tid >> 5;
    const int lane = tid & 31;
    const int gid  = lane >> 2;
    const int tig  = lane & 3;
    const int tig2 = 2 * tig;

    if (tid < 32) Ts[256 * NSTRIDE + tid] = 0;

    const int strip  = blockIdx.x * STRIPS_PER_BLK + warp;
    const bool active = (strip < NSTRIPS);
    const int strip_c = active ? strip : (NSTRIPS - 1);
    const int m0   = strip * 16;
    const int slab = blockIdx.y;

    const __half* tile = g_adjh
        + ((size_t)strip_c * SPLIT + slab) * TILE_HALVES
        + lane * OFF_TIG;                     // lane-linear global base

    const uint32_t asw = smem_u32(&As[warp][0][0]);  // warp's stage base

    // prologue: fill all ASTAGES stages (A-stream in flight during B staging)
#pragma unroll
    for (int p = 0; p < ASTAGES; p++) {
        cpa16(asw + p * 1024 + lane * 16,       tile + p * OFF_SS);
        cpa16(asw + p * 1024 + 512 + lane * 16, tile + p * OFF_SS + OFF_HALF);
        asm volatile("cp.async.commit_group;");
    }

    // stage B slab (vectorized)
    stage_B<256>(T + (size_t)slab * SLAB * F, Ts, tid);

    float acc[3][4];
#pragma unroll
    for (int t = 0; t < 3; t++)
#pragma unroll
        for (int j = 0; j < 4; j++) acc[t][j] = 0.0f;

    __syncthreads();   // B staging visible to all warps

    if (active) {
#pragma unroll
        for (int ss = 0; ss < SSTEPS; ++ss) {
            const int buf = ss % ASTAGES;      // compile-time (full unroll)

            // stage ss is complete once <= ASTAGES-1 groups remain pending
            asm volatile("cp.async.wait_group %0;" :: "n"(ASTAGES - 1));

            // consume own 16-B slots (written by this same lane)
            const uint4 va = *(const uint4*)&As[warp][buf][lane * 8];
            const uint4 vb = *(const uint4*)&As[warp][buf][256 + lane * 8];

            // refill this buffer with stage ss+ASTAGES (same-thread program
            // order makes the overwrite safe)
            {
                const int nss = ss + ASTAGES;
                if (nss < SSTEPS) {
                    cpa16(asw + buf * 1024 + lane * 16,
                          tile + nss * OFF_SS);
                    cpa16(asw + buf * 1024 + 512 + lane * 16,
                          tile + nss * OFF_SS + OFF_HALF);
                }
            }
            asm volatile("cp.async.commit_group;");

            const int kpbase = (16 * ss + 4 * tig) * NSTRIDE;
#pragma unroll
            for (int m = 0; m < 2; m++) {
                const uint32_t a0 = (m == 0) ? va.x : va.z;
                const uint32_t a1 = (m == 0) ? vb.x : vb.z;
                const uint32_t a2 = (m == 0) ? va.y : va.w;
                const uint32_t a3 = (m == 0) ? vb.y : vb.w;
                const int r0 = kpbase + 2 * m * NSTRIDE;
#pragma unroll
                for (int t = 0; t < 3; t++) {
                    const int cn = 8 * t + gid;
                    const uint32_t b0 = Ts[r0 + cn];
                    const uint32_t b1 = Ts[r0 + NSTRIDE + cn];
                    asm volatile(
                        "mma.sync.aligned.m16n8k16.row.col.f32.f16.f16.f32 "
                        "{%0,%1,%2,%3},{%4,%5,%6,%7},{%8,%9},{%0,%1,%2,%3};"
                        : "+f"(acc[t][0]), "+f"(acc[t][1]),
                          "+f"(acc[t][2]), "+f"(acc[t][3])
                        : "r"(a0), "r"(a1), "r"(a2), "r"(a3),
                          "r"(b0), "r"(b1));
                }
            }
        }

        float* po = part + (size_t)slab * NROWS * F;
#pragma unroll
        for (int t = 0; t < 3; t++) {
            const int c = 8 * t + tig2;
            if (c < F) {
                const int r0 = m0 + gid;
                const int r1 = r0 + 8;
                *(float2*)(po + (size_t)r0 * F + c) =
                    make_float2(acc[t][0], acc[t][1]);
                *(float2*)(po + (size_t)r1 * F + c) =
                    make_float2(acc[t][2], acc[t][3]);
            }
        }
    }
}

// ---------------------------------------------------------------------------
// Fused reduce + small GEMM:
//   h[row][:] = relu( sum_s P[s][row][:] + b[:] ),  T[row][:] = h[row][:] @ W
// ---------------------------------------------------------------------------
__global__ void __launch_bounds__(256)
xwred_kernel(const float* __restrict__ P, const float* __restrict__ bias,
             const float* __restrict__ W, float* __restrict__ T)
{
    __shared__ float Ws[F * F];       // 20 x 20
    __shared__ float hs[8][F];
    const int tid  = threadIdx.x;
    const int warp = tid >> 5;
    const int lane = tid & 31;
    const int row  = blockIdx.x * 8 + warp;   // grid*8 == NROWS

    for (int i = tid; i < F * F; i += 256) Ws[i] = W[i];

    if (lane < F) {
        float s = 0.f;
#pragma unroll
        for (int sl = 0; sl < SPLIT; sl++)
            s += P[(size_t)sl * NROWS * F + (size_t)row * F + lane];
        hs[warp][lane] = fmaxf(s + bias[lane], 0.f);
    }
    __syncthreads();   // Ws staged + hs visible

    if (lane < F) {
        float t = 0.f;
#pragma unroll
        for (int k = 0; k < F; k++) t += hs[warp][k] * Ws[k * F + lane];
        T[(size_t)row * F + lane] = t;
    }
}

// ---------------------------------------------------------------------------
// Reduce partials (float4): out[i] = relu( sum_s part[s][i] + bias[i%20] )
// 64-thread blocks x 782: even block distribution across all SMs.
// ---------------------------------------------------------------------------
__global__ void __launch_bounds__(64)
reduce_kernel(const float* __restrict__ part, const float* __restrict__ bias,
              float* __restrict__ out)
{
    const int i4 = (blockIdx.x * 64 + threadIdx.x) * 4;
    if (i4 < NROWS * F) {
        float4 s = make_float4(0.f, 0.f, 0.f, 0.f);
#pragma unroll
        for (int sl = 0; sl < SPLIT; sl++) {
            const float4 v = *(const float4*)(part + (size_t)sl * NROWS * F + i4);
            s.x += v.x; s.y += v.y; s.z += v.z; s.w += v.w;
        }
        float4 o;
        o.x = fmaxf(s.x + bias[(i4 + 0) % F], 0.f);
        o.y = fmaxf(s.y + bias[(i4 + 1) % F], 0.f);
        o.z = fmaxf(s.z + bias[(i4 + 2) % F], 0.f);
        o.w = fmaxf(s.w + bias[(i4 + 3) % F], 0.f);
        *(float4*)(out + i4) = o;
    }
}

// ---------------------------------------------------------------------------
// Small GEMM: T[N,20] = Hin[N,KK] @ W[KK,20].  Warp per row, lane = out col.
// ---------------------------------------------------------------------------
template <int KK>
__global__ void __launch_bounds__(256)
xw_kernel(const float* __restrict__ Hin, const float* __restrict__ W,
          float* __restrict__ T)
{
    __shared__ float Ws[KK * F];
    const int tid = threadIdx.x;
    for (int i = tid; i < KK * F; i += 256) Ws[i] = W[i];
    __syncthreads();

    const int warp = tid >> 5;
    const int lane = tid & 31;
    const int row  = blockIdx.x * 8 + warp;

    const float* h = Hin + (size_t)row * KK;
    if (lane < F) {
        float a0 = 0.f, a1 = 0.f, a2 = 0.f, a3 = 0.f;
#pragma unroll 4
        for (int k = 0; k < KK; k += 4) {
            a0 += h[k + 0] * Ws[(k + 0) * F + lane];
            a1 += h[k + 1] * Ws[(k + 1) * F + lane];
            a2 += h[k + 2] * Ws[(k + 2) * F + lane];
            a3 += h[k + 3] * Ws[(k + 3) * F + lane];
        }
        T[(size_t)row * F + lane] = (a0 + a1) + (a2 + a3);
    }
}

// ---------------------------------------------------------------------------
// Final (fused partial-reduce): out = relu( relu((sum_s P_s) @ W3 + b3) + x )
// ---------------------------------------------------------------------------
__global__ void __launch_bounds__(256)
final_kernel(const float* __restrict__ P, const float* __restrict__ W3,
             const float* __restrict__ b3, const float* __restrict__ x,
             float* __restrict__ out)
{
    __shared__ float Ws[F * D];
    __shared__ float ps[2 * F];
    const int tid = threadIdx.x;
    for (int i = tid; i < F * D; i += 256) Ws[i] = W3[i];

    const int row0 = blockIdx.x * 2;
    if (tid < 2 * F) {
        const int r = tid / F, c = tid % F;
        float s = 0.f;
#pragma unroll
        for (int sl = 0; sl < SPLIT; sl++)
            s += P[(size_t)sl * NROWS * F + (size_t)(row0 + r) * F + c];
        ps[tid] = s;
    }
    __syncthreads();

    const int r   = tid >> 7;
    const int col = tid & 127;

    float acc = b3[col];
#pragma unroll
    for (int k = 0; k < F; k++) acc += ps[r * F + k] * Ws[k * D + col];

    const float h = fmaxf(acc, 0.f);
    const size_t o = (size_t)(row0 + r) * D + col;
    out[o] = fmaxf(h + x[o], 0.f);
}

// ---------------------------------------------------------------------------
extern "C" void kernel_launch(void* const* d_in, const int* in_sizes, int n_in,
                              void* d_out, int out_size)
{
    const float* x   = (const float*)d_in[0];
    const float* adj = (const float*)d_in[1];
    const float* W1  = (const float*)d_in[2];
    const float* b1  = (const float*)d_in[3];
    const float* W2  = (const float*)d_in[4];
    const float* b2  = (const float*)d_in[5];
    const float* W3  = (const float*)d_in[6];
    const float* b3  = (const float*)d_in[7];
    float* out = (float*)d_out;

    float *T, *H, *P;
    cudaGetSymbolAddress((void**)&T, g_bufT);
    cudaGetSymbolAddress((void**)&H, g_bufH);
    cudaGetSymbolAddress((void**)&P, g_part);

    const dim3 SPMM_GRID(NSTRIP_GROUPS, SPLIT);          // 79 x 20, 256 thr
    const dim3 FUSE0_GRID(F0_GROUPS, SPLIT);             // 105 x 20, 192 thr
    const int  RED_GRID = (NROWS * F / 4 + 63) / 64;     // 782

    // T1 = x @ W1
    xw_kernel<D><<<NROWS / 8, 256>>>(x, W1, T);
    // P = partials of adj @ T1; also writes tiled fp16 adj copy
    spmm_fuse0_kernel<<<FUSE0_GRID, F0_THREADS>>>(adj, T, P);
    // T2 = relu(sum(P) + b1) @ W2   (fused reduce + xw)
    xwred_kernel<<<NROWS / 8, 256>>>(P, b1, W2, T);
    // P = partials of adj @ T2  (fp16 tiled adj)
    spmm_part_kernel<<<SPMM_GRID, 256>>>(T, P);
    // H2 = relu(sum(P) + b2)
    reduce_kernel<<<RED_GRID, 64>>>(P, b2, H);
    // P = partials of adj @ H2
    spmm_part_kernel<<<SPMM_GRID, 256>>>(H, P);
    // out = relu(relu(sum(P) @ W3 + b3) + x)
    final_kernel<<<NROWS / 2, 256>>>(P, W3, b3, x, out);
}

// round 17
// speedup vs baseline: 1.1734x; 1.1734x over previous
#include <cuda_runtime.h>
#include <cuda_fp16.h>
#include <cstdint>

// Problem constants
#define NROWS 10000
#define KDIM  10000
#define KH    10240     // fp16 adj padded cols (zeros beyond 10000)
#define F     20        // hidden width
#define D     128       // in/out width
#define NSTRIPS ((NROWS + 15) / 16)   // 625 (exact)

// K-split over the padded fp16 matrix: 20 slabs of 512 cols (32 | 512)
#define SPLIT  20
#define SLAB   512
#define SSTEPS (SLAB / 32)      // 16 supersteps (2 fp16 MMAs x 3 n-tiles each)
#define TILE_HALVES (16 * SLAB) // 8192 halves = 16 KB per (strip,slab) tile
#define STRIPS_PER_BLK 8
#define NSTRIP_GROUPS ((NSTRIPS + STRIPS_PER_BLK - 1) / STRIPS_PER_BLK)  // 79
#define ASTAGES 3               // cp.async A pipeline depth (fp16 pass)

// Intra-tile offsets IN HALVES:
#define OFF_TIG   8
#define OFF_GID   32
#define OFF_HALF  256
#define OFF_SS    512

// B smem: half2 words, [kpair 256][col stride 22] -> conflict-free LDS
#define NSTRIDE 22
#define TS_WORDS (256 * NSTRIDE + 32)

// Scratch (no allocations allowed)
__device__ float  g_bufT[NROWS * F];
__device__ float  g_bufH[NROWS * F];
__device__ float  g_part[SPLIT * NROWS * F];        // 16 MB partials
// Tiled fp16 adj: [strip 625][slab 20][ss 16][half 2][gid 8][tig 4][8 halves]
__device__ __half g_adjh[(size_t)NROWS * KH];       // 204.8 MB

__device__ __forceinline__ uint32_t pack_h2(float a, float b) {
    __half2 h = __floats2half2_rn(a, b);
    return *(uint32_t*)&h;
}
__device__ __forceinline__ uint32_t smem_u32(const void* p) {
    return (uint32_t)__cvta_generic_to_shared(p);
}
__device__ __forceinline__ void cpa16(uint32_t saddr, const void* gptr) {
    asm volatile("cp.async.cg.shared.global [%0], [%1], 16;"
                 :: "r"(saddr), "l"(gptr));
}

// Vectorized B staging: Ts[kp*22 + c] = half2(T[2kp][c], T[2kp+1][c]).
// Item (kp, c4): 2 coalesced float4 loads, pack 4 half2, 2x uint2 STS.
__device__ __forceinline__ void stage_B(const float* __restrict__ src,
                                        uint32_t* __restrict__ Ts, int tid)
{
#pragma unroll
    for (int it = 0; it < 5; ++it) {
        const int i  = it * 256 + tid;      // 0..1279
        const int kp = i / 5;
        const int c4 = i % 5;
        const float4 f0 = *(const float4*)(src + kp * 40 + 4 * c4);
        const float4 f1 = *(const float4*)(src + kp * 40 + 20 + 4 * c4);
        uint2 lo, hi;
        lo.x = pack_h2(f0.x, f1.x); lo.y = pack_h2(f0.y, f1.y);
        hi.x = pack_h2(f0.z, f1.z); hi.y = pack_h2(f0.w, f1.w);
        uint32_t* dst = &Ts[kp * NSTRIDE + 4 * c4];
        *(uint2*)(dst)     = lo;
        *(uint2*)(dst + 2) = hi;
    }
}

// ---------------------------------------------------------------------------
// PASS 0 (fused convert + GEMM) — round-15 proven version: fp32 register
// ring (depth 2), 8 warps/block, writes tiled fp16 copy, fp16 m16n8k16 MMAs.
// ---------------------------------------------------------------------------
__global__ void __launch_bounds__(256, 3)
spmm_fuse0_kernel(const float* __restrict__ adj,
                  const float* __restrict__ T,
                  float* __restrict__ part)
{
    __shared__ uint32_t Ts[TS_WORDS];   // half2 words

    const int tid  = threadIdx.x;
    const int warp = tid >> 5;
    const int lane = tid & 31;
    const int gid  = lane >> 2;
    const int tig  = lane & 3;
    const int tig2 = 2 * tig;

    if (tid < 32) Ts[256 * NSTRIDE + tid] = 0;

    const int strip  = blockIdx.x * STRIPS_PER_BLK + warp;
    const bool active = (strip < NSTRIPS);
    const int m0   = strip * 16;
    const int slab = blockIdx.y;
    const int cbase = slab * SLAB;       // fp32 col base of this slab

    const float* a_row0 = adj + (size_t)(active ? (m0 + gid) : 0) * KDIM;
    const float* a_row1 = a_row0 + (size_t)8 * KDIM;
    __half* tile_w = g_adjh
        + ((size_t)(active ? strip : 0) * SPLIT + slab) * TILE_HALVES
        + lane * OFF_TIG;               // lane-linear write base

    // stage B slab (vectorized)
    stage_B(T + (size_t)slab * SLAB * F, Ts, tid);

    float acc[3][4];
#pragma unroll
    for (int t = 0; t < 3; t++)
#pragma unroll
        for (int j = 0; j < 4; j++) acc[t][j] = 0.0f;

    // fp32 A double-buffer ring (2 supersteps deep)
    float4 r0a[2], r0b[2], r1a[2], r1b[2];
    if (active) {
#pragma unroll
        for (int p = 0; p < 2; p++) {
            const int gc = cbase + 32 * p + 8 * tig;
            const bool v = (gc < KDIM);   // 8-col group wholly valid or not
            r0a[p] = v ? *(const float4*)(a_row0 + gc)     : make_float4(0,0,0,0);
            r0b[p] = v ? *(const float4*)(a_row0 + gc + 4) : make_float4(0,0,0,0);
            r1a[p] = v ? *(const float4*)(a_row1 + gc)     : make_float4(0,0,0,0);
            r1b[p] = v ? *(const float4*)(a_row1 + gc + 4) : make_float4(0,0,0,0);
        }
    }

    __syncthreads();

    if (active) {
#pragma unroll 2
        for (int ss = 0; ss < SSTEPS; ++ss) {
            const int slot = ss & 1;
            const float4 f0a = r0a[slot], f0b = r0b[slot];
            const float4 f1a = r1a[slot], f1b = r1b[slot];

            // prefetch superstep ss+2
            {
                const int nss = ss + 2;
                if (nss < SSTEPS) {
                    const int gc = cbase + 32 * nss + 8 * tig;
                    const bool v = (gc < KDIM);
                    r0a[slot] = v ? *(const float4*)(a_row0 + gc)     : make_float4(0,0,0,0);
                    r0b[slot] = v ? *(const float4*)(a_row0 + gc + 4) : make_float4(0,0,0,0);
                    r1a[slot] = v ? *(const float4*)(a_row1 + gc)     : make_float4(0,0,0,0);
                    r1b[slot] = v ? *(const float4*)(a_row1 + gc + 4) : make_float4(0,0,0,0);
                }
            }

            // convert: va/vb match the tiled layout's register image exactly
            uint4 va, vb;
            va.x = pack_h2(f0a.x, f0a.y); va.y = pack_h2(f0a.z, f0a.w);
            va.z = pack_h2(f0b.x, f0b.y); va.w = pack_h2(f0b.z, f0b.w);
            vb.x = pack_h2(f1a.x, f1a.y); vb.y = pack_h2(f1a.z, f1a.w);
            vb.z = pack_h2(f1b.x, f1b.y); vb.w = pack_h2(f1b.z, f1b.w);

            // tiled fp16 write (warp: 2 x 512 B contiguous, lane-linear)
            *(uint4*)(tile_w + ss * OFF_SS)            = va;
            *(uint4*)(tile_w + ss * OFF_SS + OFF_HALF) = vb;

            const int kpbase = (16 * ss + 4 * tig) * NSTRIDE;
#pragma unroll
            for (int m = 0; m < 2; m++) {
                const uint32_t a0 = (m == 0) ? va.x : va.z;
                const uint32_t a1 = (m == 0) ? vb.x : vb.z;
                const uint32_t a2 = (m == 0) ? va.y : va.w;
                const uint32_t a3 = (m == 0) ? vb.y : vb.w;
                const int r0 = kpbase + 2 * m * NSTRIDE;
#pragma unroll
                for (int t = 0; t < 3; t++) {
                    const int cn = 8 * t + gid;
                    const uint32_t b0 = Ts[r0 + cn];
                    const uint32_t b1 = Ts[r0 + NSTRIDE + cn];
                    asm volatile(
                        "mma.sync.aligned.m16n8k16.row.col.f32.f16.f16.f32 "
                        "{%0,%1,%2,%3},{%4,%5,%6,%7},{%8,%9},{%0,%1,%2,%3};"
                        : "+f"(acc[t][0]), "+f"(acc[t][1]),
                          "+f"(acc[t][2]), "+f"(acc[t][3])
                        : "r"(a0), "r"(a1), "r"(a2), "r"(a3),
                          "r"(b0), "r"(b1));
                }
            }
        }

        float* po = part + (size_t)slab * NROWS * F;
#pragma unroll
        for (int t = 0; t < 3; t++) {
            const int c = 8 * t + tig2;
            if (c < F) {
                const int r0 = m0 + gid;
                const int r1 = r0 + 8;
                *(float2*)(po + (size_t)r0 * F + c) =
                    make_float2(acc[t][0], acc[t][1]);
                *(float2*)(po + (size_t)r1 * F + c) =
                    make_float2(acc[t][2], acc[t][3]);
            }
        }
    }
}

// ---------------------------------------------------------------------------
// Big GEMM partial (fp16 m16n8k16, tiled adj): passes 2 and 3.
// A path: per-warp 3-stage cp.async pipeline into smem; sync is
// cp.async.wait_group only (each lane copies exactly the 16 B it consumes).
// ---------------------------------------------------------------------------
__global__ void __launch_bounds__(256, 4)
spmm_part_kernel(const float* __restrict__ T,
                 float* __restrict__ part)
{
    __shared__ uint32_t Ts[TS_WORDS];
    __shared__ __align__(16) __half As[STRIPS_PER_BLK][ASTAGES][512]; // 24 KB

    const int tid  = threadIdx.x;
    const int warp = tid >> 5;
    const int lane = tid & 31;
    const int gid  = lane >> 2;
    const int tig  = lane & 3;
    const int tig2 = 2 * tig;

    if (tid < 32) Ts[256 * NSTRIDE + tid] = 0;

    const int strip  = blockIdx.x * STRIPS_PER_BLK + warp;
    const bool active = (strip < NSTRIPS);
    const int strip_c = active ? strip : (NSTRIPS - 1);
    const int m0   = strip * 16;
    const int slab = blockIdx.y;

    const __half* tile = g_adjh
        + ((size_t)strip_c * SPLIT + slab) * TILE_HALVES
        + lane * OFF_TIG;                     // lane-linear global base

    const uint32_t asw = smem_u32(&As[warp][0][0]);  // warp's stage base

    // prologue: fill all ASTAGES stages (A-stream in flight during B staging)
#pragma unroll
    for (int p = 0; p < ASTAGES; p++) {
        cpa16(asw + p * 1024 + lane * 16,       tile + p * OFF_SS);
        cpa16(asw + p * 1024 + 512 + lane * 16, tile + p * OFF_SS + OFF_HALF);
        asm volatile("cp.async.commit_group;");
    }

    // stage B slab (vectorized)
    stage_B(T + (size_t)slab * SLAB * F, Ts, tid);

    float acc[3][4];
#pragma unroll
    for (int t = 0; t < 3; t++)
#pragma unroll
        for (int j = 0; j < 4; j++) acc[t][j] = 0.0f;

    __syncthreads();   // B staging visible to all warps

    if (active) {
#pragma unroll
        for (int ss = 0; ss < SSTEPS; ++ss) {
            const int buf = ss % ASTAGES;      // compile-time (full unroll)

            // stage ss is complete once <= ASTAGES-1 groups remain pending
            asm volatile("cp.async.wait_group %0;" :: "n"(ASTAGES - 1));

            // consume own 16-B slots (written by this same lane)
            const uint4 va = *(const uint4*)&As[warp][buf][lane * 8];
            const uint4 vb = *(const uint4*)&As[warp][buf][256 + lane * 8];

            // refill this buffer with stage ss+ASTAGES (same-thread program
            // order makes the overwrite safe)
            {
                const int nss = ss + ASTAGES;
                if (nss < SSTEPS) {
                    cpa16(asw + buf * 1024 + lane * 16,
                          tile + nss * OFF_SS);
                    cpa16(asw + buf * 1024 + 512 + lane * 16,
                          tile + nss * OFF_SS + OFF_HALF);
                }
            }
            asm volatile("cp.async.commit_group;");

            const int kpbase = (16 * ss + 4 * tig) * NSTRIDE;
#pragma unroll
            for (int m = 0; m < 2; m++) {
                const uint32_t a0 = (m == 0) ? va.x : va.z;
                const uint32_t a1 = (m == 0) ? vb.x : vb.z;
                const uint32_t a2 = (m == 0) ? va.y : va.w;
                const uint32_t a3 = (m == 0) ? vb.y : vb.w;
                const int r0 = kpbase + 2 * m * NSTRIDE;
#pragma unroll
                for (int t = 0; t < 3; t++) {
                    const int cn = 8 * t + gid;
                    const uint32_t b0 = Ts[r0 + cn];
                    const uint32_t b1 = Ts[r0 + NSTRIDE + cn];
                    asm volatile(
                        "mma.sync.aligned.m16n8k16.row.col.f32.f16.f16.f32 "
                        "{%0,%1,%2,%3},{%4,%5,%6,%7},{%8,%9},{%0,%1,%2,%3};"
                        : "+f"(acc[t][0]), "+f"(acc[t][1]),
                          "+f"(acc[t][2]), "+f"(acc[t][3])
                        : "r"(a0), "r"(a1), "r"(a2), "r"(a3),
                          "r"(b0), "r"(b1));
                }
            }
        }

        float* po = part + (size_t)slab * NROWS * F;
#pragma unroll
        for (int t = 0; t < 3; t++) {
            const int c = 8 * t + tig2;
            if (c < F) {
                const int r0 = m0 + gid;
                const int r1 = r0 + 8;
                *(float2*)(po + (size_t)r0 * F + c) =
                    make_float2(acc[t][0], acc[t][1]);
                *(float2*)(po + (size_t)r1 * F + c) =
                    make_float2(acc[t][2], acc[t][3]);
            }
        }
    }
}

// ---------------------------------------------------------------------------
// Fused reduce + small GEMM:
//   h[row][:] = relu( sum_s P[s][row][:] + b[:] ),  T[row][:] = h[row][:] @ W
// ---------------------------------------------------------------------------
__global__ void __launch_bounds__(256)
xwred_kernel(const float* __restrict__ P, const float* __restrict__ bias,
             const float* __restrict__ W, float* __restrict__ T)
{
    __shared__ float Ws[F * F];       // 20 x 20
    __shared__ float hs[8][F];
    const int tid  = threadIdx.x;
    const int warp = tid >> 5;
    const int lane = tid & 31;
    const int row  = blockIdx.x * 8 + warp;   // grid*8 == NROWS

    for (int i = tid; i < F * F; i += 256) Ws[i] = W[i];

    if (lane < F) {
        float s = 0.f;
#pragma unroll
        for (int sl = 0; sl < SPLIT; sl++)
            s += P[(size_t)sl * NROWS * F + (size_t)row * F + lane];
        hs[warp][lane] = fmaxf(s + bias[lane], 0.f);
    }
    __syncthreads();   // Ws staged + hs visible

    if (lane < F) {
        float t = 0.f;
#pragma unroll
        for (int k = 0; k < F; k++) t += hs[warp][k] * Ws[k * F + lane];
        T[(size_t)row * F + lane] = t;
    }
}

// ---------------------------------------------------------------------------
// Reduce partials (float4): out[i] = relu( sum_s part[s][i] + bias[i%20] )
// 64-thread blocks x 782: even block distribution across all SMs.
// ---------------------------------------------------------------------------
__global__ void __launch_bounds__(64)
reduce_kernel(const float* __restrict__ part, const float* __restrict__ bias,
              float* __restrict__ out)
{
    const int i4 = (blockIdx.x * 64 + threadIdx.x) * 4;
    if (i4 < NROWS * F) {
        float4 s = make_float4(0.f, 0.f, 0.f, 0.f);
#pragma unroll
        for (int sl = 0; sl < SPLIT; sl++) {
            const float4 v = *(const float4*)(part + (size_t)sl * NROWS * F + i4);
            s.x += v.x; s.y += v.y; s.z += v.z; s.w += v.w;
        }
        float4 o;
        o.x = fmaxf(s.x + bias[(i4 + 0) % F], 0.f);
        o.y = fmaxf(s.y + bias[(i4 + 1) % F], 0.f);
        o.z = fmaxf(s.z + bias[(i4 + 2) % F], 0.f);
        o.w = fmaxf(s.w + bias[(i4 + 3) % F], 0.f);
        *(float4*)(out + i4) = o;
    }
}

// ---------------------------------------------------------------------------
// Small GEMM: T[N,20] = Hin[N,KK] @ W[KK,20].  Warp per row, lane = out col.
// Input rows staged into smem cooperatively (coalesced) so the k-loop runs
// on smem broadcasts instead of repeated gmem loads.
// ---------------------------------------------------------------------------
template <int KK>
__global__ void __launch_bounds__(256)
xw_kernel(const float* __restrict__ Hin, const float* __restrict__ W,
          float* __restrict__ T)
{
    __shared__ float Ws[KK * F];
    __shared__ float xs[8 * KK];
    const int tid = threadIdx.x;
    for (int i = tid; i < KK * F; i += 256) Ws[i] = W[i];
    {
        // stage this block's 8 input rows (contiguous, 16-B aligned)
        const float4* src = (const float4*)(Hin + (size_t)blockIdx.x * 8 * KK);
        for (int i = tid; i < (8 * KK) / 4; i += 256)
            ((float4*)xs)[i] = src[i];
    }
    __syncthreads();

    const int warp = tid >> 5;
    const int lane = tid & 31;
    const int row  = blockIdx.x * 8 + warp;   // grid*8 == NROWS exactly

    const float* h = xs + warp * KK;
    if (lane < F) {
        float a0 = 0.f, a1 = 0.f, a2 = 0.f, a3 = 0.f;
#pragma unroll 4
        for (int k = 0; k < KK; k += 4) {
            a0 += h[k + 0] * Ws[(k + 0) * F + lane];
            a1 += h[k + 1] * Ws[(k + 1) * F + lane];
            a2 += h[k + 2] * Ws[(k + 2) * F + lane];
            a3 += h[k + 3] * Ws[(k + 3) * F + lane];
        }
        T[(size_t)row * F + lane] = (a0 + a1) + (a2 + a3);
    }
}

// ---------------------------------------------------------------------------
// Final (fused partial-reduce): out = relu( relu((sum_s P_s) @ W3 + b3) + x )
// ---------------------------------------------------------------------------
__global__ void __launch_bounds__(256)
final_kernel(const float* __restrict__ P, const float* __restrict__ W3,
             const float* __restrict__ b3, const float* __restrict__ x,
             float* __restrict__ out)
{
    __shared__ float Ws[F * D];
    __shared__ float ps[2 * F];
    const int tid = threadIdx.x;
    for (int i = tid; i < F * D; i += 256) Ws[i] = W3[i];

    const int row0 = blockIdx.x * 2;
    if (tid < 2 * F) {
        const int r = tid / F, c = tid % F;
        float s = 0.f;
#pragma unroll
        for (int sl = 0; sl < SPLIT; sl++)
            s += P[(size_t)sl * NROWS * F + (size_t)(row0 + r) * F + c];
        ps[tid] = s;
    }
    __syncthreads();

    const int r   = tid >> 7;
    const int col = tid & 127;

    float acc = b3[col];
#pragma unroll
    for (int k = 0; k < F; k++) acc += ps[r * F + k] * Ws[k * D + col];

    const float h = fmaxf(acc, 0.f);
    const size_t o = (size_t)(row0 + r) * D + col;
    out[o] = fmaxf(h + x[o], 0.f);
}

// ---------------------------------------------------------------------------
extern "C" void kernel_launch(void* const* d_in, const int* in_sizes, int n_in,
                              void* d_out, int out_size)
{
    const float* x   = (const float*)d_in[0];
    const float* adj = (const float*)d_in[1];
    const float* W1  = (const float*)d_in[2];
    const float* b1  = (const float*)d_in[3];
    const float* W2  = (const float*)d_in[4];
    const float* b2  = (const float*)d_in[5];
    const float* W3  = (const float*)d_in[6];
    const float* b3  = (const float*)d_in[7];
    float* out = (float*)d_out;

    float *T, *H, *P;
    cudaGetSymbolAddress((void**)&T, g_bufT);
    cudaGetSymbolAddress((void**)&H, g_bufH);
    cudaGetSymbolAddress((void**)&P, g_part);

    const dim3 SPMM_GRID(NSTRIP_GROUPS, SPLIT);          // 79 x 20, 256 thr
    const int  RED_GRID = (NROWS * F / 4 + 63) / 64;     // 782

    // T1 = x @ W1
    xw_kernel<D><<<NROWS / 8, 256>>>(x, W1, T);
    // P = partials of adj @ T1; also writes tiled fp16 adj copy
    spmm_fuse0_kernel<<<SPMM_GRID, 256>>>(adj, T, P);
    // T2 = relu(sum(P) + b1) @ W2   (fused reduce + xw)
    xwred_kernel<<<NROWS / 8, 256>>>(P, b1, W2, T);
    // P = partials of adj @ T2  (fp16 tiled adj)
    spmm_part_kernel<<<SPMM_GRID, 256>>>(T, P);
    // H2 = relu(sum(P) + b2)
    reduce_kernel<<<RED_GRID, 64>>>(P, b2, H);
    // P = partials of adj @ H2
    spmm_part_kernel<<<SPMM_GRID, 256>>>(H, P);
    // out = relu(relu(sum(P) @ W3 + b3) + x)
    final_kernel<<<NROWS / 2, 256>>>(P, W3, b3, x, out);
}